// round 11
// baseline (speedup 1.0000x reference)
#include <cuda_runtime.h>
#include <cuda_fp16.h>
#include <mma.h>
#include <math.h>

using namespace nvcuda;

#define BB    16
#define NN    1024
#define UU    64
#define F1    128          // 2U
#define MTOT  (BB*NN)      // 16384
#define MAXD  128
#define ALPHA 0.2f

// ---------------- scratch (device globals; no allocation) ----------------
__device__ __half g_xsh[MTOT * F1];     // 4 MB  fp16 [X|state]
__device__ __half g_w1h[F1 * F1];       // 32 KB fp16 W1
__device__ __half g_w2h[F1 * UU];       // 16 KB fp16 W2
__device__ __half g_h1h[MTOT * F1];     // 4 MB  fp16 gather payload, layer 1
__device__ __half g_h2h[MTOT * UU];     // 2 MB  fp16 gather payload, layer 2
__device__ __half g_rsh[MTOT * UU];     // 2 MB  fp16 r*state
__device__ float  g_ssrc1[MTOT];
__device__ float  g_sdst1[MTOT];
__device__ float  g_ssrc2[MTOT];
__device__ float  g_sdst2[MTOT];
__device__ float  g_z[MTOT * UU];       // 4 MB
__device__ int    g_nbr[NN * MAXD];     // 512 KB
__device__ int    g_deg[NN];

// ---------------- prep: adjacency lists + fp16 conversions ---------------
// blocks 0..127: neighbor lists.  blocks 128..191: convert [X|state] rows.
// block 128 additionally converts W1, W2.
__global__ void prep_kernel(const float* __restrict__ adj,
                            const float* __restrict__ X,
                            const float* __restrict__ state,
                            const float* __restrict__ W1,
                            const float* __restrict__ W2) {
    int tid = threadIdx.x;
    if (blockIdx.x < 128) {
        int warp = blockIdx.x * 8 + (tid >> 5);
        int lane = tid & 31;
        int base = 0;
        for (int j0 = 0; j0 < NN; j0 += 32) {
            float v = adj[(size_t)warp * NN + j0 + lane];
            unsigned mask = __ballot_sync(0xffffffffu, v > 0.0f);
            if (v > 0.0f) {
                int pos = base + __popc(mask & ((1u << lane) - 1u));
                if (pos < MAXD) g_nbr[warp * MAXD + pos] = j0 + lane;
            }
            base += __popc(mask);
        }
        if (lane == 0) g_deg[warp] = base < MAXD ? base : MAXD;
        return;
    }
    int bid = blockIdx.x - 128;          // 0..63
    int m = bid * 256 + tid;             // one row per thread
    const float4* xr = (const float4*)(X + (size_t)m * 64);      // 16 float4
    const float4* sr = (const float4*)(state + (size_t)m * 64);  // 16 float4
    uint4* dst = (uint4*)(g_xsh + (size_t)m * F1);               // 16 uint4
    #pragma unroll
    for (int i = 0; i < 16; i++) {
        float4 f0 = (i < 8) ? xr[2 * i]     : sr[2 * (i - 8)];
        float4 f1 = (i < 8) ? xr[2 * i + 1] : sr[2 * (i - 8) + 1];
        __half2 h0 = __floats2half2_rn(f0.x, f0.y);
        __half2 h1 = __floats2half2_rn(f0.z, f0.w);
        __half2 h2 = __floats2half2_rn(f1.x, f1.y);
        __half2 h3 = __floats2half2_rn(f1.z, f1.w);
        uint4 u;
        u.x = *(unsigned*)&h0; u.y = *(unsigned*)&h1;
        u.z = *(unsigned*)&h2; u.w = *(unsigned*)&h3;
        dst[i] = u;
    }
    if (bid == 0) {
        const float2* w1 = (const float2*)W1;
        const float2* w2 = (const float2*)W2;
        __half2* d1 = (__half2*)g_w1h;
        __half2* d2 = (__half2*)g_w2h;
        for (int idx = tid; idx < F1 * F1 / 2; idx += 256) {
            float2 v = w1[idx];
            d1[idx] = __floats2half2_rn(v.x, v.y);
        }
        for (int idx = tid; idx < F1 * UU / 2; idx += 256) {
            float2 v = w2[idx];
            d2[idx] = __floats2half2_rn(v.x, v.y);
        }
    }
}

// ---------------- GEMM1 (HMMA): 32x128 tile, grid 512 --------------------
// smem: As 32x128 fp16 (8KB) + Bs 128x128 fp16 (32KB); Cs fp32 overlays.
__global__ void gemm1_kernel(const float* __restrict__ a1) {
    __shared__ __align__(16) char smem[40960];
    __half* As = (__half*)smem;                 // [32][128]
    __half* Bs = (__half*)(smem + 8192);        // [128][128]
    float*  Cs = (float*)smem;                  // [32][136] after sync

    int tid = threadIdx.x;
    int m0 = blockIdx.x * 32;

    // stage A: 512 uint4 (8 halves each)
    #pragma unroll
    for (int i = 0; i < 2; i++) {
        int idx = tid + 256 * i;
        int r = idx >> 4, s = idx & 15;
        ((uint4*)As)[idx] = ((const uint4*)(g_xsh + (size_t)(m0 + r) * F1))[s];
    }
    // stage B: 2048 uint4
    #pragma unroll
    for (int i = 0; i < 8; i++) {
        int idx = tid + 256 * i;
        ((uint4*)Bs)[idx] = ((const uint4*)g_w1h)[idx];
    }
    __syncthreads();

    int w = tid >> 5;          // col frag w: cols w*16

    wmma::fragment<wmma::accumulator, 16, 16, 16, float> cf[2];
    wmma::fill_fragment(cf[0], 0.0f);
    wmma::fill_fragment(cf[1], 0.0f);

    #pragma unroll
    for (int k8 = 0; k8 < 8; k8++) {
        wmma::fragment<wmma::matrix_b, 16, 16, 16, __half, wmma::row_major> bf;
        wmma::load_matrix_sync(bf, Bs + k8 * 16 * 128 + w * 16, 128);
        wmma::fragment<wmma::matrix_a, 16, 16, 16, __half, wmma::row_major> af0, af1;
        wmma::load_matrix_sync(af0, As + k8 * 16, 128);
        wmma::load_matrix_sync(af1, As + 16 * 128 + k8 * 16, 128);
        wmma::mma_sync(cf[0], af0, bf, cf[0]);
        wmma::mma_sync(cf[1], af1, bf, cf[1]);
    }
    __syncthreads();

    wmma::store_matrix_sync(Cs + w * 16, cf[0], 136, wmma::mem_row_major);
    wmma::store_matrix_sync(Cs + 16 * 136 + w * 16, cf[1], 136, wmma::mem_row_major);
    __syncthreads();

    // epilogue: 8 threads per row, 16 cols each
    int row = tid >> 3;
    int oc = tid & 7;
    int m = m0 + row;
    const float* crow = Cs + row * 136 + oc * 16;
    float ps = 0.0f, pd = 0.0f;
    #pragma unroll
    for (int c = 0; c < 16; c += 2) {
        float c0 = crow[c], c1 = crow[c + 1];
        int col = oc * 16 + c;
        ps += c0 * a1[col]      + c1 * a1[col + 1];
        pd += c0 * a1[F1 + col] + c1 * a1[F1 + col + 1];
        *(__half2*)&g_h1h[(size_t)m * F1 + col] = __floats2half2_rn(c0, c1);
    }
    #pragma unroll
    for (int o = 4; o; o >>= 1) {
        ps += __shfl_xor_sync(0xffffffffu, ps, o);
        pd += __shfl_xor_sync(0xffffffffu, pd, o);
    }
    if (oc == 0) { g_ssrc1[m] = ps; g_sdst1[m] = pd; }
}

// ---------------- attention layer 1 + sigmoid gate -----------------------
__global__ void att1_kernel(const float* __restrict__ state) {
    int bi = blockIdx.x;
    int b = bi >> 10;
    int i = bi & (NN - 1);
    int tid = threadIdx.x;          // 0..63
    __shared__ float w[MAXD];
    __shared__ int   js[MAXD];
    __shared__ float red[4];

    int deg = g_deg[i];
    float si = g_ssrc1[b * NN + i];
    float e0 = -3.0e38f, e1 = -3.0e38f;
    if (tid < deg) {
        int j = g_nbr[i * MAXD + tid];
        js[tid] = j;
        float x = si + g_sdst1[b * NN + j];
        e0 = (x > 0.0f) ? x : ALPHA * x;
    }
    int t1 = tid + 64;
    if (t1 < deg) {
        int j = g_nbr[i * MAXD + t1];
        js[t1] = j;
        float x = si + g_sdst1[b * NN + j];
        e1 = (x > 0.0f) ? x : ALPHA * x;
    }
    float mx = fmaxf(e0, e1);
    #pragma unroll
    for (int o = 16; o; o >>= 1) mx = fmaxf(mx, __shfl_xor_sync(0xffffffffu, mx, o));
    if ((tid & 31) == 0) red[tid >> 5] = mx;
    __syncthreads();
    mx = fmaxf(red[0], red[1]);

    float w0 = (tid < deg) ? expf(e0 - mx) : 0.0f;
    float w1 = (t1  < deg) ? expf(e1 - mx) : 0.0f;
    w[tid] = w0;
    if (t1 < deg) w[t1] = w1;
    float sm = w0 + w1;
    #pragma unroll
    for (int o = 16; o; o >>= 1) sm += __shfl_xor_sync(0xffffffffu, sm, o);
    if ((tid & 31) == 0) red[2 + (tid >> 5)] = sm;
    __syncthreads();
    float inv = 1.0f / (red[2] + red[3]);

    const __half2* hb = (const __half2*)g_h1h + (size_t)b * NN * 64 + tid;
    float ax = 0.0f, ay = 0.0f;
    int t = 0;
    for (; t + 4 <= deg; t += 4) {
        float ww0 = w[t],  ww1 = w[t+1], ww2 = w[t+2], ww3 = w[t+3];
        int ja = js[t], jb = js[t+1], jc = js[t+2], jd = js[t+3];
        float2 f0 = __half22float2(hb[(size_t)ja * 64]);
        float2 f1 = __half22float2(hb[(size_t)jb * 64]);
        float2 f2 = __half22float2(hb[(size_t)jc * 64]);
        float2 f3 = __half22float2(hb[(size_t)jd * 64]);
        ax += ww0*f0.x + ww1*f1.x + ww2*f2.x + ww3*f3.x;
        ay += ww0*f0.y + ww1*f1.y + ww2*f2.y + ww3*f3.y;
    }
    for (; t < deg; t++) {
        float ww = w[t];
        float2 f = __half22float2(hb[(size_t)js[t] * 64]);
        ax += ww * f.x;
        ay += ww * f.y;
    }
    ax *= inv; ay *= inv;
    float g0 = 1.0f / (1.0f + expf(-ax));
    float g1 = 1.0f / (1.0f + expf(-ay));

    int m = b * NN + i;
    if (tid < 32) {                  // channels < 64 -> r * state (fp16)
        float2 st = *(const float2*)&state[(size_t)m * UU + 2 * tid];
        ((__half2*)g_rsh)[(size_t)m * 32 + tid] =
            __floats2half2_rn(g0 * st.x, g1 * st.y);
    } else {                         // channels >= 64 -> z (fp32)
        float2 z2 = make_float2(g0, g1);
        *(float2*)&g_z[(size_t)m * UU + 2 * (tid - 32)] = z2;
    }
}

// ---------------- GEMM2 (HMMA): 32x64 tile, grid 512 ---------------------
// smem: As 32x128 fp16 (8KB) + Bs 128x64 fp16 (16KB); Cs fp32 overlays.
__global__ void gemm2_kernel(const float* __restrict__ a2) {
    __shared__ __align__(16) char smem[24576];
    __half* As = (__half*)smem;                 // [32][128]
    __half* Bs = (__half*)(smem + 8192);        // [128][64]
    float*  Cs = (float*)smem;                  // [32][72] after sync

    int tid = threadIdx.x;
    int m0 = blockIdx.x * 32;

    // stage A: 512 uint4; cols 0-63 from g_xsh (X half), 64-127 from g_rsh
    #pragma unroll
    for (int i = 0; i < 2; i++) {
        int idx = tid + 256 * i;
        int r = idx >> 4, s = idx & 15;
        int m = m0 + r;
        uint4 v = (s < 8)
            ? ((const uint4*)(g_xsh + (size_t)m * F1))[s]
            : ((const uint4*)(g_rsh + (size_t)m * UU))[s - 8];
        ((uint4*)As)[idx] = v;
    }
    // stage B: 1024 uint4
    #pragma unroll
    for (int i = 0; i < 4; i++) {
        int idx = tid + 256 * i;
        ((uint4*)Bs)[idx] = ((const uint4*)g_w2h)[idx];
    }
    __syncthreads();

    int w = tid >> 5;
    int rg = w >> 2;           // row group 0..1
    int cg = w & 3;            // col group 0..3

    wmma::fragment<wmma::accumulator, 16, 16, 16, float> cf;
    wmma::fill_fragment(cf, 0.0f);

    #pragma unroll
    for (int k8 = 0; k8 < 8; k8++) {
        wmma::fragment<wmma::matrix_a, 16, 16, 16, __half, wmma::row_major> af;
        wmma::fragment<wmma::matrix_b, 16, 16, 16, __half, wmma::row_major> bf;
        wmma::load_matrix_sync(af, As + rg * 16 * 128 + k8 * 16, 128);
        wmma::load_matrix_sync(bf, Bs + k8 * 16 * 64 + cg * 16, 64);
        wmma::mma_sync(cf, af, bf, cf);
    }
    __syncthreads();

    wmma::store_matrix_sync(Cs + rg * 16 * 72 + cg * 16, cf, 72, wmma::mem_row_major);
    __syncthreads();

    // epilogue: 8 threads per row, 8 cols each
    int row = tid >> 3;
    int oc = tid & 7;
    int m = m0 + row;
    const float* crow = Cs + row * 72 + oc * 8;
    float ps = 0.0f, pd = 0.0f;
    #pragma unroll
    for (int c = 0; c < 8; c += 2) {
        float c0 = crow[c], c1 = crow[c + 1];
        int col = oc * 8 + c;
        ps += c0 * a2[col]      + c1 * a2[col + 1];
        pd += c0 * a2[UU + col] + c1 * a2[UU + col + 1];
        *(__half2*)&g_h2h[(size_t)m * UU + col] = __floats2half2_rn(c0, c1);
    }
    #pragma unroll
    for (int o = 4; o; o >>= 1) {
        ps += __shfl_xor_sync(0xffffffffu, ps, o);
        pd += __shfl_xor_sync(0xffffffffu, pd, o);
    }
    if (oc == 0) { g_ssrc2[m] = ps; g_sdst2[m] = pd; }
}

// ---------------- attention layer 2 + tanh + GRU blend -------------------
__global__ void att2_kernel(const float* __restrict__ state,
                            float* __restrict__ out) {
    int bi = blockIdx.x;
    int b = bi >> 10;
    int i = bi & (NN - 1);
    int tid = threadIdx.x;          // 0..63
    __shared__ float w[MAXD];
    __shared__ int   js[MAXD];
    __shared__ float red[4];

    int deg = g_deg[i];
    float si = g_ssrc2[b * NN + i];
    float e0 = -3.0e38f, e1 = -3.0e38f;
    if (tid < deg) {
        int j = g_nbr[i * MAXD + tid];
        js[tid] = j;
        float x = si + g_sdst2[b * NN + j];
        e0 = (x > 0.0f) ? x : ALPHA * x;
    }
    int t1 = tid + 64;
    if (t1 < deg) {
        int j = g_nbr[i * MAXD + t1];
        js[t1] = j;
        float x = si + g_sdst2[b * NN + j];
        e1 = (x > 0.0f) ? x : ALPHA * x;
    }
    float mx = fmaxf(e0, e1);
    #pragma unroll
    for (int o = 16; o; o >>= 1) mx = fmaxf(mx, __shfl_xor_sync(0xffffffffu, mx, o));
    if ((tid & 31) == 0) red[tid >> 5] = mx;
    __syncthreads();
    mx = fmaxf(red[0], red[1]);

    float w0 = (tid < deg) ? expf(e0 - mx) : 0.0f;
    float w1 = (t1  < deg) ? expf(e1 - mx) : 0.0f;
    w[tid] = w0;
    if (t1 < deg) w[t1] = w1;
    float sm = w0 + w1;
    #pragma unroll
    for (int o = 16; o; o >>= 1) sm += __shfl_xor_sync(0xffffffffu, sm, o);
    if ((tid & 31) == 0) red[2 + (tid >> 5)] = sm;
    __syncthreads();
    float inv = 1.0f / (red[2] + red[3]);

    if (tid < 32) {
        const __half2* hb = (const __half2*)g_h2h + (size_t)b * NN * 32 + tid;
        float ax = 0.0f, ay = 0.0f;
        int t = 0;
        for (; t + 4 <= deg; t += 4) {
            float ww0 = w[t], ww1 = w[t+1], ww2 = w[t+2], ww3 = w[t+3];
            int ja = js[t], jb = js[t+1], jc = js[t+2], jd = js[t+3];
            float2 f0 = __half22float2(hb[(size_t)ja * 32]);
            float2 f1 = __half22float2(hb[(size_t)jb * 32]);
            float2 f2 = __half22float2(hb[(size_t)jc * 32]);
            float2 f3 = __half22float2(hb[(size_t)jd * 32]);
            ax += ww0*f0.x + ww1*f1.x + ww2*f2.x + ww3*f3.x;
            ay += ww0*f0.y + ww1*f1.y + ww2*f2.y + ww3*f3.y;
        }
        for (; t < deg; t++) {
            float ww = w[t];
            float2 f = __half22float2(hb[(size_t)js[t] * 32]);
            ax += ww * f.x;
            ay += ww * f.y;
        }
        ax *= inv; ay *= inv;
        float h0 = tanhf(ax);
        float h1v = tanhf(ay);

        int m = b * NN + i;
        float2 st = *(const float2*)&state[(size_t)m * UU + 2 * tid];
        float2 z2 = *(const float2*)&g_z[(size_t)m * UU + 2 * tid];
        float2 o2;
        o2.x = z2.x * st.x + (1.0f - z2.x) * h0;
        o2.y = z2.y * st.y + (1.0f - z2.y) * h1v;
        *(float2*)&out[(size_t)m * UU + 2 * tid] = o2;
    }
}

// ---------------- launch -------------------------------------------------
extern "C" void kernel_launch(void* const* d_in, const int* in_sizes, int n_in,
                              void* d_out, int out_size) {
    const float* X     = (const float*)d_in[0];
    const float* state = (const float*)d_in[1];
    const float* adj   = (const float*)d_in[2];
    const float* W1    = (const float*)d_in[3];
    const float* a1    = (const float*)d_in[4];
    const float* W2    = (const float*)d_in[5];
    const float* a2    = (const float*)d_in[6];
    float* out = (float*)d_out;

    prep_kernel<<<192, 256>>>(adj, X, state, W1, W2);
    gemm1_kernel<<<MTOT / 32, 256>>>(a1);
    att1_kernel<<<MTOT, 64>>>(state);
    gemm2_kernel<<<MTOT / 32, 256>>>(a2);
    att2_kernel<<<MTOT, 64>>>(state, out);
}

// round 12
// speedup vs baseline: 1.1902x; 1.1902x over previous
#include <cuda_runtime.h>
#include <cuda_fp16.h>
#include <math.h>

#define BB    16
#define NN    1024
#define UU    64
#define F1    128          // 2U
#define MTOT  (BB*NN)      // 16384
#define MAXD  128
#define ALPHA 0.2f

// ---------------- scratch (device globals; no allocation) ----------------
__device__ __half g_xsh[MTOT * F1];     // 4 MB  fp16 [X|state]
__device__ __half g_h1h[MTOT * F1];     // 4 MB  fp16 gather payload, layer 1
__device__ __half g_h2h[MTOT * UU];     // 2 MB  fp16 gather payload, layer 2
__device__ __half g_rsh[MTOT * UU];     // 2 MB  fp16 r*state
__device__ float  g_ssrc1[MTOT];
__device__ float  g_sdst1[MTOT];
__device__ float  g_ssrc2[MTOT];
__device__ float  g_sdst2[MTOT];
__device__ float  g_z[MTOT * UU];       // 4 MB
__device__ float  g_wa1[256];           // [W1@a1_src | W1@a1_dst]
__device__ float  g_wa2[256];           // [W2@a2_src | W2@a2_dst]
__device__ int    g_nbr[NN * MAXD];     // 512 KB
__device__ int    g_deg[NN];

// ---------------- raw tensor-core mma ------------------------------------
__device__ __forceinline__ void mma16816(float* c, const unsigned* a, uint2 b) {
    asm volatile(
        "mma.sync.aligned.m16n8k16.row.col.f32.f16.f16.f32 "
        "{%0,%1,%2,%3}, {%4,%5,%6,%7}, {%8,%9}, {%0,%1,%2,%3};"
        : "+f"(c[0]), "+f"(c[1]), "+f"(c[2]), "+f"(c[3])
        : "r"(a[0]), "r"(a[1]), "r"(a[2]), "r"(a[3]), "r"(b.x), "r"(b.y));
}

// ---------------- prep: adj lists + fp16 convert + W@a vectors -----------
// blocks 0..127: neighbor lists. 128..191: convert [X|state]. 192: W@a.
__global__ void prep_kernel(const float* __restrict__ adj,
                            const float* __restrict__ X,
                            const float* __restrict__ state,
                            const float* __restrict__ W1,
                            const float* __restrict__ a1,
                            const float* __restrict__ W2,
                            const float* __restrict__ a2) {
    int tid = threadIdx.x;
    if (blockIdx.x < 128) {
        int warp = blockIdx.x * 8 + (tid >> 5);
        int lane = tid & 31;
        int base = 0;
        for (int j0 = 0; j0 < NN; j0 += 32) {
            float v = adj[(size_t)warp * NN + j0 + lane];
            unsigned mask = __ballot_sync(0xffffffffu, v > 0.0f);
            if (v > 0.0f) {
                int pos = base + __popc(mask & ((1u << lane) - 1u));
                if (pos < MAXD) g_nbr[warp * MAXD + pos] = j0 + lane;
            }
            base += __popc(mask);
        }
        if (lane == 0) g_deg[warp] = base < MAXD ? base : MAXD;
        return;
    }
    if (blockIdx.x < 192) {
        // coalesced fp16 conversion: idx = m*32 + c2 over 512K float2 each
        const float2* Xf = (const float2*)X;
        const float2* Sf = (const float2*)state;
        __half2* dst = (__half2*)g_xsh;
        int idx0 = (blockIdx.x - 128) * 256 + tid;
        for (int idx = idx0; idx < MTOT * 32; idx += 64 * 256) {
            int m = idx >> 5, c = idx & 31;
            float2 v = Xf[idx];
            dst[m * 64 + c] = __floats2half2_rn(v.x, v.y);
            float2 s = Sf[idx];
            dst[m * 64 + 32 + c] = __floats2half2_rn(s.x, s.y);
        }
        return;
    }
    // block 192: Wa vectors. thread t handles k-row t.
    if (tid < 128) {
        float ws = 0.0f, wd = 0.0f;
        const float* row = W1 + tid * 128;
        #pragma unroll 4
        for (int o = 0; o < 128; o++) {
            float w = row[o];
            ws += w * a1[o];
            wd += w * a1[128 + o];
        }
        g_wa1[tid] = ws; g_wa1[128 + tid] = wd;
        float ws2 = 0.0f, wd2 = 0.0f;
        const float* row2 = W2 + tid * 64;
        #pragma unroll 4
        for (int o = 0; o < 64; o++) {
            float w = row2[o];
            ws2 += w * a2[o];
            wd2 += w * a2[64 + o];
        }
        g_wa2[tid] = ws2; g_wa2[128 + tid] = wd2;
    }
}

// ---------------- GEMM1: h1 = Xs @ W1, barrier-free mma ------------------
// grid 128 x 256thr. One sync (B-frag + Wa smem). Warp = 16-row tile x n128.
__global__ void gemm1_kernel(const float* __restrict__ W1) {
    __shared__ uint2 bf[16 * 8 * 32];   // 32 KB: B fragments [nb][k][lane]
    __shared__ float sWs[128], sWd[128];
    int tid = threadIdx.x;

    for (int e = tid; e < 16 * 8 * 32; e += 256) {
        int lane = e & 31, k = (e >> 5) & 7, nb = e >> 8;
        int t = lane & 3, g = lane >> 2;
        int n = nb * 8 + g;
        int kr = k * 16 + 2 * t;
        __half2 r0 = __floats2half2_rn(W1[kr * 128 + n],       W1[(kr + 1) * 128 + n]);
        __half2 r1 = __floats2half2_rn(W1[(kr + 8) * 128 + n], W1[(kr + 9) * 128 + n]);
        uint2 u; u.x = *(unsigned*)&r0; u.y = *(unsigned*)&r1;
        bf[e] = u;
    }
    if (tid < 128) { sWs[tid] = g_wa1[tid]; sWd[tid] = g_wa1[128 + tid]; }
    __syncthreads();

    int w = tid >> 5, lane = tid & 31;
    int t = lane & 3, g = lane >> 2;
    int m0 = (blockIdx.x * 8 + w) * 16;

    const __half* A0 = g_xsh + (size_t)(m0 + g) * F1 + 2 * t;
    const __half* A8 = A0 + 8 * F1;
    unsigned a[8][4];
    #pragma unroll
    for (int k = 0; k < 8; k++) {
        a[k][0] = *(const unsigned*)(A0 + k * 16);
        a[k][1] = *(const unsigned*)(A8 + k * 16);
        a[k][2] = *(const unsigned*)(A0 + k * 16 + 8);
        a[k][3] = *(const unsigned*)(A8 + k * 16 + 8);
    }

    // fused s = x . (W@a) for rows m0+g and m0+g+8
    float ps0 = 0, pd0 = 0, ps8 = 0, pd8 = 0;
    #pragma unroll
    for (int k = 0; k < 8; k++) {
        int c0 = k * 16 + 2 * t;
        float2 f;
        f = __half22float2(*(__half2*)&a[k][0]);
        ps0 += f.x * sWs[c0] + f.y * sWs[c0 + 1];
        pd0 += f.x * sWd[c0] + f.y * sWd[c0 + 1];
        f = __half22float2(*(__half2*)&a[k][2]);
        ps0 += f.x * sWs[c0 + 8] + f.y * sWs[c0 + 9];
        pd0 += f.x * sWd[c0 + 8] + f.y * sWd[c0 + 9];
        f = __half22float2(*(__half2*)&a[k][1]);
        ps8 += f.x * sWs[c0] + f.y * sWs[c0 + 1];
        pd8 += f.x * sWd[c0] + f.y * sWd[c0 + 1];
        f = __half22float2(*(__half2*)&a[k][3]);
        ps8 += f.x * sWs[c0 + 8] + f.y * sWs[c0 + 9];
        pd8 += f.x * sWd[c0 + 8] + f.y * sWd[c0 + 9];
    }
    #pragma unroll
    for (int o = 1; o <= 2; o <<= 1) {
        ps0 += __shfl_xor_sync(0xffffffffu, ps0, o);
        pd0 += __shfl_xor_sync(0xffffffffu, pd0, o);
        ps8 += __shfl_xor_sync(0xffffffffu, ps8, o);
        pd8 += __shfl_xor_sync(0xffffffffu, pd8, o);
    }
    if (t == 0) {
        g_ssrc1[m0 + g] = ps0;     g_sdst1[m0 + g] = pd0;
        g_ssrc1[m0 + 8 + g] = ps8; g_sdst1[m0 + 8 + g] = pd8;
    }

    float c[16][4];
    #pragma unroll
    for (int nb = 0; nb < 16; nb++)
        #pragma unroll
        for (int i = 0; i < 4; i++) c[nb][i] = 0.0f;

    #pragma unroll
    for (int k = 0; k < 8; k++)
        #pragma unroll
        for (int nb = 0; nb < 16; nb++)
            mma16816(c[nb], a[k], bf[(nb * 8 + k) * 32 + lane]);

    __half* H0 = g_h1h + (size_t)(m0 + g) * F1 + 2 * t;
    __half* H8 = H0 + 8 * F1;
    #pragma unroll
    for (int nb = 0; nb < 16; nb++) {
        *(__half2*)(H0 + nb * 8) = __floats2half2_rn(c[nb][0], c[nb][1]);
        *(__half2*)(H8 + nb * 8) = __floats2half2_rn(c[nb][2], c[nb][3]);
    }
}

// ---------------- attention layer 1 + sigmoid gate -----------------------
__global__ void att1_kernel(const float* __restrict__ state) {
    int bi = blockIdx.x;
    int b = bi >> 10;
    int i = bi & (NN - 1);
    int tid = threadIdx.x;          // 0..63
    __shared__ float w[MAXD];
    __shared__ int   js[MAXD];
    __shared__ float red[4];

    int deg = g_deg[i];
    float si = g_ssrc1[b * NN + i];
    float e0 = -3.0e38f, e1 = -3.0e38f;
    if (tid < deg) {
        int j = g_nbr[i * MAXD + tid];
        js[tid] = j;
        float x = si + g_sdst1[b * NN + j];
        e0 = (x > 0.0f) ? x : ALPHA * x;
    }
    int t1 = tid + 64;
    if (t1 < deg) {
        int j = g_nbr[i * MAXD + t1];
        js[t1] = j;
        float x = si + g_sdst1[b * NN + j];
        e1 = (x > 0.0f) ? x : ALPHA * x;
    }
    float mx = fmaxf(e0, e1);
    #pragma unroll
    for (int o = 16; o; o >>= 1) mx = fmaxf(mx, __shfl_xor_sync(0xffffffffu, mx, o));
    if ((tid & 31) == 0) red[tid >> 5] = mx;
    __syncthreads();
    mx = fmaxf(red[0], red[1]);

    float w0 = (tid < deg) ? expf(e0 - mx) : 0.0f;
    float w1 = (t1  < deg) ? expf(e1 - mx) : 0.0f;
    w[tid] = w0;
    if (t1 < deg) w[t1] = w1;
    float sm = w0 + w1;
    #pragma unroll
    for (int o = 16; o; o >>= 1) sm += __shfl_xor_sync(0xffffffffu, sm, o);
    if ((tid & 31) == 0) red[2 + (tid >> 5)] = sm;
    __syncthreads();
    float inv = 1.0f / (red[2] + red[3]);

    const __half2* hb = (const __half2*)g_h1h + (size_t)b * NN * 64 + tid;
    float ax = 0.0f, ay = 0.0f;
    int t = 0;
    for (; t + 4 <= deg; t += 4) {
        float ww0 = w[t],  ww1 = w[t+1], ww2 = w[t+2], ww3 = w[t+3];
        int ja = js[t], jb = js[t+1], jc = js[t+2], jd = js[t+3];
        float2 f0 = __half22float2(hb[(size_t)ja * 64]);
        float2 f1 = __half22float2(hb[(size_t)jb * 64]);
        float2 f2 = __half22float2(hb[(size_t)jc * 64]);
        float2 f3 = __half22float2(hb[(size_t)jd * 64]);
        ax += ww0*f0.x + ww1*f1.x + ww2*f2.x + ww3*f3.x;
        ay += ww0*f0.y + ww1*f1.y + ww2*f2.y + ww3*f3.y;
    }
    for (; t < deg; t++) {
        float ww = w[t];
        float2 f = __half22float2(hb[(size_t)js[t] * 64]);
        ax += ww * f.x;
        ay += ww * f.y;
    }
    ax *= inv; ay *= inv;
    float g0 = 1.0f / (1.0f + expf(-ax));
    float g1 = 1.0f / (1.0f + expf(-ay));

    int m = b * NN + i;
    if (tid < 32) {                  // channels < 64 -> r * state (fp16)
        float2 st = *(const float2*)&state[(size_t)m * UU + 2 * tid];
        ((__half2*)g_rsh)[(size_t)m * 32 + tid] =
            __floats2half2_rn(g0 * st.x, g1 * st.y);
    } else {                         // channels >= 64 -> z (fp32)
        float2 z2 = make_float2(g0, g1);
        *(float2*)&g_z[(size_t)m * UU + 2 * (tid - 32)] = z2;
    }
}

// ---------------- GEMM2: h2 = [X | r*state] @ W2, barrier-free -----------
// grid 128 x 256thr. A: ksteps 0-3 from g_xsh (X cols), 4-7 from g_rsh.
__global__ void gemm2_kernel(const float* __restrict__ W2) {
    __shared__ uint2 bf[8 * 8 * 32];    // 16 KB
    __shared__ float sWs[128], sWd[128];
    int tid = threadIdx.x;

    for (int e = tid; e < 8 * 8 * 32; e += 256) {
        int lane = e & 31, k = (e >> 5) & 7, nb = e >> 8;
        int t = lane & 3, g = lane >> 2;
        int n = nb * 8 + g;
        int kr = k * 16 + 2 * t;
        __half2 r0 = __floats2half2_rn(W2[kr * 64 + n],       W2[(kr + 1) * 64 + n]);
        __half2 r1 = __floats2half2_rn(W2[(kr + 8) * 64 + n], W2[(kr + 9) * 64 + n]);
        uint2 u; u.x = *(unsigned*)&r0; u.y = *(unsigned*)&r1;
        bf[e] = u;
    }
    if (tid < 128) { sWs[tid] = g_wa2[tid]; sWd[tid] = g_wa2[128 + tid]; }
    __syncthreads();

    int w = tid >> 5, lane = tid & 31;
    int t = lane & 3, g = lane >> 2;
    int m0 = (blockIdx.x * 8 + w) * 16;

    const __half* X0 = g_xsh + (size_t)(m0 + g) * F1 + 2 * t;       // cols 0..63
    const __half* X8 = X0 + 8 * F1;
    const __half* R0 = g_rsh + (size_t)(m0 + g) * UU + 2 * t;       // cols 64..127
    const __half* R8 = R0 + 8 * UU;
    unsigned a[8][4];
    #pragma unroll
    for (int k = 0; k < 4; k++) {
        a[k][0] = *(const unsigned*)(X0 + k * 16);
        a[k][1] = *(const unsigned*)(X8 + k * 16);
        a[k][2] = *(const unsigned*)(X0 + k * 16 + 8);
        a[k][3] = *(const unsigned*)(X8 + k * 16 + 8);
    }
    #pragma unroll
    for (int k = 4; k < 8; k++) {
        a[k][0] = *(const unsigned*)(R0 + (k - 4) * 16);
        a[k][1] = *(const unsigned*)(R8 + (k - 4) * 16);
        a[k][2] = *(const unsigned*)(R0 + (k - 4) * 16 + 8);
        a[k][3] = *(const unsigned*)(R8 + (k - 4) * 16 + 8);
    }

    float ps0 = 0, pd0 = 0, ps8 = 0, pd8 = 0;
    #pragma unroll
    for (int k = 0; k < 8; k++) {
        int c0 = k * 16 + 2 * t;
        float2 f;
        f = __half22float2(*(__half2*)&a[k][0]);
        ps0 += f.x * sWs[c0] + f.y * sWs[c0 + 1];
        pd0 += f.x * sWd[c0] + f.y * sWd[c0 + 1];
        f = __half22float2(*(__half2*)&a[k][2]);
        ps0 += f.x * sWs[c0 + 8] + f.y * sWs[c0 + 9];
        pd0 += f.x * sWd[c0 + 8] + f.y * sWd[c0 + 9];
        f = __half22float2(*(__half2*)&a[k][1]);
        ps8 += f.x * sWs[c0] + f.y * sWs[c0 + 1];
        pd8 += f.x * sWd[c0] + f.y * sWd[c0 + 1];
        f = __half22float2(*(__half2*)&a[k][3]);
        ps8 += f.x * sWs[c0 + 8] + f.y * sWs[c0 + 9];
        pd8 += f.x * sWd[c0 + 8] + f.y * sWd[c0 + 9];
    }
    #pragma unroll
    for (int o = 1; o <= 2; o <<= 1) {
        ps0 += __shfl_xor_sync(0xffffffffu, ps0, o);
        pd0 += __shfl_xor_sync(0xffffffffu, pd0, o);
        ps8 += __shfl_xor_sync(0xffffffffu, ps8, o);
        pd8 += __shfl_xor_sync(0xffffffffu, pd8, o);
    }
    if (t == 0) {
        g_ssrc2[m0 + g] = ps0;     g_sdst2[m0 + g] = pd0;
        g_ssrc2[m0 + 8 + g] = ps8; g_sdst2[m0 + 8 + g] = pd8;
    }

    float c[8][4];
    #pragma unroll
    for (int nb = 0; nb < 8; nb++)
        #pragma unroll
        for (int i = 0; i < 4; i++) c[nb][i] = 0.0f;

    #pragma unroll
    for (int k = 0; k < 8; k++)
        #pragma unroll
        for (int nb = 0; nb < 8; nb++)
            mma16816(c[nb], a[k], bf[(nb * 8 + k) * 32 + lane]);

    __half* H0 = g_h2h + (size_t)(m0 + g) * UU + 2 * t;
    __half* H8 = H0 + 8 * UU;
    #pragma unroll
    for (int nb = 0; nb < 8; nb++) {
        *(__half2*)(H0 + nb * 8) = __floats2half2_rn(c[nb][0], c[nb][1]);
        *(__half2*)(H8 + nb * 8) = __floats2half2_rn(c[nb][2], c[nb][3]);
    }
}

// ---------------- attention layer 2 + tanh + GRU blend -------------------
__global__ void att2_kernel(const float* __restrict__ state,
                            float* __restrict__ out) {
    int bi = blockIdx.x;
    int b = bi >> 10;
    int i = bi & (NN - 1);
    int tid = threadIdx.x;          // 0..63
    __shared__ float w[MAXD];
    __shared__ int   js[MAXD];
    __shared__ float red[4];

    int deg = g_deg[i];
    float si = g_ssrc2[b * NN + i];
    float e0 = -3.0e38f, e1 = -3.0e38f;
    if (tid < deg) {
        int j = g_nbr[i * MAXD + tid];
        js[tid] = j;
        float x = si + g_sdst2[b * NN + j];
        e0 = (x > 0.0f) ? x : ALPHA * x;
    }
    int t1 = tid + 64;
    if (t1 < deg) {
        int j = g_nbr[i * MAXD + t1];
        js[t1] = j;
        float x = si + g_sdst2[b * NN + j];
        e1 = (x > 0.0f) ? x : ALPHA * x;
    }
    float mx = fmaxf(e0, e1);
    #pragma unroll
    for (int o = 16; o; o >>= 1) mx = fmaxf(mx, __shfl_xor_sync(0xffffffffu, mx, o));
    if ((tid & 31) == 0) red[tid >> 5] = mx;
    __syncthreads();
    mx = fmaxf(red[0], red[1]);

    float w0 = (tid < deg) ? expf(e0 - mx) : 0.0f;
    float w1 = (t1  < deg) ? expf(e1 - mx) : 0.0f;
    w[tid] = w0;
    if (t1 < deg) w[t1] = w1;
    float sm = w0 + w1;
    #pragma unroll
    for (int o = 16; o; o >>= 1) sm += __shfl_xor_sync(0xffffffffu, sm, o);
    if ((tid & 31) == 0) red[2 + (tid >> 5)] = sm;
    __syncthreads();
    float inv = 1.0f / (red[2] + red[3]);

    if (tid < 32) {
        const __half2* hb = (const __half2*)g_h2h + (size_t)b * NN * 32 + tid;
        float ax = 0.0f, ay = 0.0f;
        int t = 0;
        for (; t + 4 <= deg; t += 4) {
            float ww0 = w[t], ww1 = w[t+1], ww2 = w[t+2], ww3 = w[t+3];
            int ja = js[t], jb = js[t+1], jc = js[t+2], jd = js[t+3];
            float2 f0 = __half22float2(hb[(size_t)ja * 32]);
            float2 f1 = __half22float2(hb[(size_t)jb * 32]);
            float2 f2 = __half22float2(hb[(size_t)jc * 32]);
            float2 f3 = __half22float2(hb[(size_t)jd * 32]);
            ax += ww0*f0.x + ww1*f1.x + ww2*f2.x + ww3*f3.x;
            ay += ww0*f0.y + ww1*f1.y + ww2*f2.y + ww3*f3.y;
        }
        for (; t < deg; t++) {
            float ww = w[t];
            float2 f = __half22float2(hb[(size_t)js[t] * 32]);
            ax += ww * f.x;
            ay += ww * f.y;
        }
        ax *= inv; ay *= inv;
        float h0 = tanhf(ax);
        float h1v = tanhf(ay);

        int m = b * NN + i;
        float2 st = *(const float2*)&state[(size_t)m * UU + 2 * tid];
        float2 z2 = *(const float2*)&g_z[(size_t)m * UU + 2 * tid];
        float2 o2;
        o2.x = z2.x * st.x + (1.0f - z2.x) * h0;
        o2.y = z2.y * st.y + (1.0f - z2.y) * h1v;
        *(float2*)&out[(size_t)m * UU + 2 * tid] = o2;
    }
}

// ---------------- launch -------------------------------------------------
extern "C" void kernel_launch(void* const* d_in, const int* in_sizes, int n_in,
                              void* d_out, int out_size) {
    const float* X     = (const float*)d_in[0];
    const float* state = (const float*)d_in[1];
    const float* adj   = (const float*)d_in[2];
    const float* W1    = (const float*)d_in[3];
    const float* a1    = (const float*)d_in[4];
    const float* W2    = (const float*)d_in[5];
    const float* a2    = (const float*)d_in[6];
    float* out = (float*)d_out;

    prep_kernel<<<193, 256>>>(adj, X, state, W1, a1, W2, a2);
    gemm1_kernel<<<128, 256>>>(W1);
    att1_kernel<<<MTOT, 64>>>(state);
    gemm2_kernel<<<128, 256>>>(W2);
    att2_kernel<<<MTOT, 64>>>(state, out);
}